// round 6
// baseline (speedup 1.0000x reference)
#include <cuda_runtime.h>
#include <math.h>

#define SIZE 1000
#define NPTS 8
#define MAXCAND 512

// ---------------------------------------------------------------------------
// tanh(100000*x) with exact fp32 saturation fast path:
// tanhf(t) rounds to exactly +/-1.0f for |t| >= ~9.02, i.e. |x| >= 1e-4.
// ---------------------------------------------------------------------------
__device__ __forceinline__ float vi_sgn(float x) {
    if (fabsf(x) >= 1e-4f) return copysignf(1.0f, x);
    return tanhf(100000.0f * x);
}

// Exact mask element (pre-transpose i=row, j=col), faithful to the reference.
__device__ __forceinline__ float vi_maskval(float a, float b, int i, int j) {
    float x1 = vi_sgn(a - (float)j);
    float y1 = vi_sgn(b - (float)(i + 1));
    float x3 = vi_sgn(a - (float)(j + 1));
    float y3 = vi_sgn(b - (float)i);
    float m1 = vi_sgn(y1 * x1);
    float m3 = vi_sgn(y3 * x3);
    return (1.0f - m1 * m3) * 0.5f;
}

// Transposed mask with zero padding: mt(p,q) = mask(i=q, j=p)
__device__ __forceinline__ float vi_mt(float a, float b, int p, int q) {
    if (p < 0 || p >= SIZE || q < 0 || q >= SIZE) return 0.0f;
    return vi_maskval(a, b, q, p);
}

// ---------------------------------------------------------------------------
// Single fused kernel: per-block candidate recompute (cheap closed form with
// exact fallback) + 40MB float4 zero-fill with inline scatter-max.
//
// Closed form (both fracs saturated): transposed mask is 1 on the cross arms
// {p=jc} U {q=ic} minus the center; plus-conv hits 4 only at (jc,ic) =>
// relu(conv-3) = 1.0 at exactly that cell (needs jc,ic in [1,998]).
// ---------------------------------------------------------------------------
__global__ void vi_fused_kernel(const float* __restrict__ z_pos,
                                const int* __restrict__ z_cls,
                                float4* __restrict__ out4, int n4) {
    __shared__ int   s_off[MAXCAND];
    __shared__ float s_val[MAXCAND];
    __shared__ int   s_cnt;
    __shared__ int   s_hit;

    if (threadIdx.x == 0) { s_cnt = 0; s_hit = 0; }
    __syncthreads();

    if (threadIdx.x < NPTS) {
        int n = threadIdx.x;
        float a = z_pos[2 * n + 0] * 1000.0f;
        float b = z_pos[2 * n + 1] * 1000.0f;
        int   c = z_cls[n];
        int  jc = (int)floorf(a);
        int  ic = (int)floorf(b);
        float fa = a - (float)jc;
        float fb = b - (float)ic;
        bool sat = (fa >= 1e-4f) && (fa <= 1.0f - 1e-4f) &&
                   (fb >= 1e-4f) && (fb <= 1.0f - 1e-4f);
        if (sat) {
            // closed form: single 1.0 at the cross intersection (if interior)
            if (jc >= 1 && jc <= SIZE - 2 && ic >= 1 && ic <= SIZE - 2) {
                int k = atomicAdd(&s_cnt, 1);
                s_off[k] = (jc * SIZE + ic) * 10 + c;
                s_val[k] = 1.0f;
            }
        } else {
            // rare near-integer band: exact 7x7 window evaluation
            for (int t = 0; t < 49; t++) {
                int p = jc + (t % 7) - 3;
                int q = ic + (t / 7) - 3;
                if (p < 0 || p >= SIZE || q < 0 || q >= SIZE) continue;
                float conv = vi_mt(a, b, p - 1, q) + vi_mt(a, b, p + 1, q) +
                             vi_mt(a, b, p, q - 1) + vi_mt(a, b, p, q + 1);
                float v = conv - 3.0f;
                if (v > 0.0f) {
                    int k = atomicAdd(&s_cnt, 1);
                    s_off[k] = (p * SIZE + q) * 10 + c;
                    s_val[k] = v;
                }
            }
        }
    }
    __syncthreads();

    // Does any candidate fall in this block's output range?
    int e_base = (blockIdx.x * blockDim.x) * 4;       // first element this block
    int e_span = blockDim.x * 4;                      // elements per block
    if (threadIdx.x == 0) {
        int cnt = s_cnt;
        int hit = 0;
        for (int k = 0; k < cnt; k++) {
            unsigned d = (unsigned)(s_off[k] - e_base);
            hit |= (d < (unsigned)e_span);
        }
        s_hit = hit;
    }
    __syncthreads();

    int i = blockIdx.x * blockDim.x + threadIdx.x;
    if (i >= n4) return;

    float4 v = make_float4(0.f, 0.f, 0.f, 0.f);
    if (s_hit) {                                      // only <=8 blocks take this
        int e = i * 4;
        int cnt = s_cnt;
        for (int k = 0; k < cnt; k++) {
            int d = s_off[k] - e;
            float val = s_val[k];
            if (d == 0) v.x = fmaxf(v.x, val);
            else if (d == 1) v.y = fmaxf(v.y, val);
            else if (d == 2) v.z = fmaxf(v.z, val);
            else if (d == 3) v.w = fmaxf(v.w, val);
        }
    }
    out4[i] = v;
}

extern "C" void kernel_launch(void* const* d_in, const int* in_sizes, int n_in,
                              void* d_out, int out_size) {
    const float* z_pos = (const float*)d_in[0];  // [8,2] fp32
    const int*   z_cls = (const int*)d_in[1];    // [8] int32
    float* out = (float*)d_out;                  // [1000,1000,10] fp32

    int n4 = out_size / 4;                       // 2,500,000 (exact: 10M % 4 == 0)
    int threads = 256;
    int blocks = (n4 + threads - 1) / threads;
    vi_fused_kernel<<<blocks, threads>>>(z_pos, z_cls, (float4*)out, n4);
}